// round 15
// baseline (speedup 1.0000x reference)
#include <cuda_runtime.h>
#include <cuda_fp16.h>
#include <math_constants.h>
#include <cstdint>

// Problem constants
#define BATCH   4
#define SEQ     2048
#define DMODEL  1024
#define NHEADS  16
#define HDIM    64
#define TOKENS  (BATCH * SEQ)   // 8192

#define LOG2E 1.4426950408889634f
#define SCL2E (0.125f * LOG2E)   // softmax scale folded into exponent

// ---------------------------------------------------------------------------
// Scratch (allocation-free rule: __device__ globals)
// ---------------------------------------------------------------------------
__device__ __half g_xh [TOKENS * DMODEL];
__device__ __half g_qh [TOKENS * DMODEL];
__device__ __half g_kh [TOKENS * DMODEL];
__device__ __half g_vh [TOKENS * DMODEL];
__device__ __half g_ch [TOKENS * DMODEL];
__device__ __half g_wqh[DMODEL * DMODEL];
__device__ __half g_wkh[DMODEL * DMODEL];
__device__ __half g_wvh[DMODEL * DMODEL];
__device__ __half g_woh[DMODEL * DMODEL];

// ---------------------------------------------------------------------------
// PTX helpers (sm_80-baseline only: cp.async, ldmatrix, mma.sync)
// ---------------------------------------------------------------------------
__device__ __forceinline__ uint32_t smem_u32(const void* p) {
    uint32_t a;
    asm("{ .reg .u64 t; cvta.to.shared.u64 t, %1; cvt.u32.u64 %0, t; }"
        : "=r"(a) : "l"(p));
    return a;
}

__device__ __forceinline__ void cp_async16(uint32_t smem, const void* gmem) {
    asm volatile("cp.async.cg.shared.global [%0], [%1], 16;\n"
                 :: "r"(smem), "l"(gmem));
}
#define CP_COMMIT() asm volatile("cp.async.commit_group;\n" ::: "memory")
#define CP_WAIT(n)  asm volatile("cp.async.wait_group %0;\n" :: "n"(n) : "memory")

__device__ __forceinline__ void ldsm_x4(uint32_t* r, uint32_t addr) {
    asm volatile("ldmatrix.sync.aligned.m8n8.x4.shared.b16 {%0,%1,%2,%3}, [%4];"
                 : "=r"(r[0]), "=r"(r[1]), "=r"(r[2]), "=r"(r[3]) : "r"(addr));
}

__device__ __forceinline__ void ldsm_x4_trans(uint32_t* r, uint32_t addr) {
    asm volatile("ldmatrix.sync.aligned.m8n8.x4.trans.shared.b16 {%0,%1,%2,%3}, [%4];"
                 : "=r"(r[0]), "=r"(r[1]), "=r"(r[2]), "=r"(r[3]) : "r"(addr));
}

__device__ __forceinline__ void mma_f16(float* c, const uint32_t* a,
                                        uint32_t b0, uint32_t b1) {
    asm volatile(
        "mma.sync.aligned.m16n8k16.row.col.f32.f16.f16.f32 "
        "{%0,%1,%2,%3}, {%4,%5,%6,%7}, {%8,%9}, {%0,%1,%2,%3};"
        : "+f"(c[0]), "+f"(c[1]), "+f"(c[2]), "+f"(c[3])
        : "r"(a[0]), "r"(a[1]), "r"(a[2]), "r"(a[3]), "r"(b0), "r"(b1));
}

__device__ __forceinline__ uint32_t pack_f16(float x, float y) {
    __half2 t = __floats2half2_rn(x, y);
    return *(uint32_t*)&t;
}

// Single-MUFU exp2 (approx, ftz). -inf -> 0, which is what the mask needs.
__device__ __forceinline__ float ex2f(float x) {
    float r;
    asm("ex2.approx.ftz.f32 %0, %1;" : "=f"(r) : "f"(x));
    return r;
}

// ---------------------------------------------------------------------------
// Preprocessing (single launch): grid.y==0 converts x; 1..4 convert weights.
// ---------------------------------------------------------------------------
__global__ void prep_all_kernel(
    const float* __restrict__ x,
    const float* __restrict__ wq, const float* __restrict__ wk,
    const float* __restrict__ wv, const float* __restrict__ wo,
    __half* __restrict__ xh,
    __half* __restrict__ wqh, __half* __restrict__ wkh,
    __half* __restrict__ wvh, __half* __restrict__ woh)
{
    const float* in;
    __half* out;
    int n;
    switch (blockIdx.y) {
        case 0:  in = x;  out = xh;  n = TOKENS * DMODEL; break;
        case 1:  in = wq; out = wqh; n = DMODEL * DMODEL; break;
        case 2:  in = wk; out = wkh; n = DMODEL * DMODEL; break;
        case 3:  in = wv; out = wvh; n = DMODEL * DMODEL; break;
        default: in = wo; out = woh; n = DMODEL * DMODEL; break;
    }
    int i = (blockIdx.x * blockDim.x + threadIdx.x) * 4;
    if (i >= n) return;
    float4 v = *(const float4*)(in + i);
    ((__half2*)(out + i))[0] = __floats2half2_rn(v.x, v.y);
    ((__half2*)(out + i))[1] = __floats2half2_rn(v.z, v.w);
}

// ---------------------------------------------------------------------------
// Single-pass fp16 GEMM core: CTA 128x128, BK=64, 256 threads (8 warps,
// 2x4), warp tile 64x32, 3-stage cp.async (110,592 B), launch_bounds(256,2).
// (round-14 config, known good)
// ---------------------------------------------------------------------------
#define GK_BK       64
#define GK_ROW_B    144
#define GK_TILE_B   (128 * GK_ROW_B)           // 18432
#define GK_NCHUNKS  (DMODEL / GK_BK)           // 16
#define G1_STAGE_B  (2 * GK_TILE_B)            // 36864
#define G1_STAGES   3
#define G1_SMEM     (G1_STAGES * G1_STAGE_B)   // 110592

__device__ __forceinline__ void g1_mainloop(
    const __half* __restrict__ A, const __half* __restrict__ B,
    int bm, int bn, uint32_t sbase, int tid, float acc[4][4][4])
{
    const int wid  = tid >> 5;
    const int lane = tid & 31;
    const int warp_m = wid >> 2;
    const int warp_n = wid & 3;

    auto load_chunk = [&](int c, int st) {
        const int k0 = c * GK_BK;
        const uint32_t sb = sbase + st * G1_STAGE_B;
#pragma unroll
        for (int i = tid; i < 1024; i += 256) {
            const int r = i >> 3;
            const int q = i & 7;
            cp_async16(sb + r * GK_ROW_B + q * 16,
                       A + (size_t)(bm + r) * DMODEL + k0 + q * 8);
            cp_async16(sb + GK_TILE_B + r * GK_ROW_B + q * 16,
                       B + (size_t)(bn + r) * DMODEL + k0 + q * 8);
        }
        CP_COMMIT();
    };

    load_chunk(0, 0);
    load_chunk(1, 1);

    const uint32_t lrow16 = (uint32_t)(lane & 15);
    const uint32_t lcolb  = (uint32_t)((lane >> 4) << 4);

    for (int c = 0; c < GK_NCHUNKS; c++) {
        const int st = c % G1_STAGES;
        if (c + 1 < GK_NCHUNKS) { CP_WAIT(1); } else { CP_WAIT(0); }
        __syncthreads();
        if (c + 2 < GK_NCHUNKS) load_chunk(c + 2, (c + 2) % G1_STAGES);

        const uint32_t stg = sbase + st * G1_STAGE_B;
        const uint32_t a_r = (uint32_t)(warp_m * 64) + lrow16;
        const uint32_t b_r = (uint32_t)(warp_n * 32) + lrow16;

#pragma unroll
        for (int ks = 0; ks < 4; ks++) {
            const uint32_t kb = lcolb + ks * 32;
            uint32_t ah[4][4], bb[2][4];
#pragma unroll
            for (int mi = 0; mi < 4; mi++)
                ldsm_x4(ah[mi], stg + (a_r + mi * 16) * GK_ROW_B + kb);
#pragma unroll
            for (int p = 0; p < 2; p++)
                ldsm_x4(bb[p], stg + GK_TILE_B + (b_r + p * 16) * GK_ROW_B + kb);
#pragma unroll
            for (int mi = 0; mi < 4; mi++)
#pragma unroll
                for (int ni = 0; ni < 4; ni++) {
                    const int p = ni >> 1, s = ni & 1;
                    mma_f16(acc[mi][ni], ah[mi], bb[p][s], bb[p][s + 2]);
                }
        }
        __syncthreads();
    }
}

// ---------------------------------------------------------------------------
// Fused QKV projection (single-pass fp16): grid.z selects W/output.
// ---------------------------------------------------------------------------
__global__ __launch_bounds__(256, 2) void gemm_qkv(
    const __half* __restrict__ xh,
    const __half* __restrict__ wqh, const __half* __restrict__ wkh,
    const __half* __restrict__ wvh,
    __half* __restrict__ qh, __half* __restrict__ kh, __half* __restrict__ vh)
{
    extern __shared__ char smem[];
    const uint32_t sbase = smem_u32(smem);
    const int tid = threadIdx.x;
    const int bm = blockIdx.y * 128;
    const int bn = blockIdx.x * 128;

    const __half* B;
    __half* C;
    if (blockIdx.z == 0)      { B = wqh; C = qh; }
    else if (blockIdx.z == 1) { B = wkh; C = kh; }
    else                      { B = wvh; C = vh; }

    float acc[4][4][4];
#pragma unroll
    for (int i = 0; i < 4; i++)
#pragma unroll
        for (int j = 0; j < 4; j++)
#pragma unroll
            for (int r = 0; r < 4; r++) acc[i][j][r] = 0.f;

    g1_mainloop(xh, B, bm, bn, sbase, tid, acc);

    const int wid  = tid >> 5;
    const int lane = tid & 31;
    const int warp_m = wid >> 2;
    const int warp_n = wid & 3;
    const int er = lane >> 2;
    const int ec = (lane & 3) * 2;
#pragma unroll
    for (int mi = 0; mi < 4; mi++) {
        const int row0 = bm + warp_m * 64 + mi * 16 + er;
#pragma unroll
        for (int ni = 0; ni < 4; ni++) {
            const int col = bn + warp_n * 32 + ni * 8 + ec;
            *(uint32_t*)(C + (size_t)row0 * DMODEL + col) =
                pack_f16(acc[mi][ni][0], acc[mi][ni][1]);
            *(uint32_t*)(C + (size_t)(row0 + 8) * DMODEL + col) =
                pack_f16(acc[mi][ni][2], acc[mi][ni][3]);
        }
    }
}

// ---------------------------------------------------------------------------
// Output projection (single-pass fp16): fp32 out + bias.
// ---------------------------------------------------------------------------
__global__ __launch_bounds__(256, 2) void gemm_out(
    const __half* __restrict__ Ah, const __half* __restrict__ Bh,
    const float* __restrict__ bias, float* __restrict__ C)
{
    extern __shared__ char smem[];
    const uint32_t sbase = smem_u32(smem);
    const int tid = threadIdx.x;
    const int bm = blockIdx.y * 128;
    const int bn = blockIdx.x * 128;

    float acc[4][4][4];
#pragma unroll
    for (int i = 0; i < 4; i++)
#pragma unroll
        for (int j = 0; j < 4; j++)
#pragma unroll
            for (int r = 0; r < 4; r++) acc[i][j][r] = 0.f;

    g1_mainloop(Ah, Bh, bm, bn, sbase, tid, acc);

    const int wid  = tid >> 5;
    const int lane = tid & 31;
    const int warp_m = wid >> 2;
    const int warp_n = wid & 3;
    const int er = lane >> 2;
    const int ec = (lane & 3) * 2;
#pragma unroll
    for (int mi = 0; mi < 4; mi++) {
        const int row0 = bm + warp_m * 64 + mi * 16 + er;
#pragma unroll
        for (int ni = 0; ni < 4; ni++) {
            const int col = bn + warp_n * 32 + ni * 8 + ec;
            const float b0 = bias[col];
            const float b1 = bias[col + 1];
            float2 v0 = make_float2(acc[mi][ni][0] + b0, acc[mi][ni][1] + b1);
            float2 v1 = make_float2(acc[mi][ni][2] + b0, acc[mi][ni][3] + b1);
            *(float2*)(C + (size_t)row0 * DMODEL + col)       = v0;
            *(float2*)(C + (size_t)(row0 + 8) * DMODEL + col) = v1;
        }
    }
}

// ---------------------------------------------------------------------------
// Flash attention v4 (causal): fp16 MMA, fp32 softmax (ex2.approx).
// 128-key K/V tiles processed as two sequential 64-key halves per barrier
// window (identical arithmetic to v3, half the CP_WAIT/__syncthreads).
// 2-stage pipeline. SMEM: Q 18432 + 2 x 36864 = 92160 -> 2 CTAs/SM.
// ---------------------------------------------------------------------------
#define FA_ROW_B    144
#define FA_Q_B      (128 * FA_ROW_B)        // 18432
#define FA_K_ARR_B  (128 * FA_ROW_B)        // 18432 (128 keys of K)
#define FA_STAGE_B  (2 * FA_K_ARR_B)        // 36864 (K + V)
#define FA_KV_OFF   FA_Q_B
#define FA_SMEM     (FA_Q_B + 2 * FA_STAGE_B)  // 92160

__global__ __launch_bounds__(256, 2) void flash_mma_kernel(
    const __half* __restrict__ Q, const __half* __restrict__ K,
    const __half* __restrict__ V, __half* __restrict__ C)
{
    extern __shared__ char fsm[];
    const uint32_t sbase = smem_u32(fsm);

    const int tid  = threadIdx.x;
    const int wid  = tid >> 5;
    const int lane = tid & 31;
    const int qt = blockIdx.x;
    const int h  = blockIdx.y;
    const int b  = blockIdx.z;

    const int q0_tok = b * SEQ + qt * 128;
    const int qrow_w = qt * 128 + wid * 16;

    // ---- load Q tile (128 rows x 64 fp16) into SMEM ----
    {
        const __half* Qg = Q + (size_t)q0_tok * DMODEL + h * HDIM;
#pragma unroll
        for (int i = tid; i < 1024; i += 256) {
            const int r  = i >> 3;
            const int c8 = i & 7;
            cp_async16(sbase + r * FA_ROW_B + c8 * 16,
                       Qg + (size_t)r * DMODEL + c8 * 8);
        }
        CP_COMMIT();
    }

    float o[8][4];
    float m[2], l[2];
#pragma unroll
    for (int i = 0; i < 8; i++)
#pragma unroll
        for (int j = 0; j < 4; j++) o[i][j] = 0.f;
    m[0] = m[1] = -CUDART_INF_F;
    l[0] = l[1] = 0.f;

    const uint32_t a_loff = (uint32_t)((lane & 15) * FA_ROW_B + ((lane >> 4) << 4));
    const uint32_t k_loff = (uint32_t)(((lane & 7) + ((lane >> 4) << 3)) * FA_ROW_B
                                       + (((lane >> 3) & 1) << 4));
    const uint32_t v_loff = (uint32_t)(((lane & 7) + (((lane >> 3) & 1) << 3)) * FA_ROW_B
                                       + ((lane >> 4) << 4));

    const uint32_t q_w = sbase + (uint32_t)(wid * 16) * FA_ROW_B + a_loff;

    const __half* Kh = K + h * HDIM;
    const __half* Vh = V + h * HDIM;

    // Load a 128-key K/V tile into stage stg.
    auto load_tile = [&](int kt, int stg) {
        const size_t tok0 = (size_t)(b * SEQ + kt * 128);
        const uint32_t sb = sbase + FA_KV_OFF + stg * FA_STAGE_B;
#pragma unroll
        for (int i = tid; i < 1024; i += 256) {
            const int r  = i >> 3;
            const int c8 = i & 7;
            cp_async16(sb + r * FA_ROW_B + c8 * 16,
                       Kh + (tok0 + r) * DMODEL + c8 * 8);
            cp_async16(sb + FA_K_ARR_B + r * FA_ROW_B + c8 * 16,
                       Vh + (tok0 + r) * DMODEL + c8 * 8);
        }
        CP_COMMIT();
    };

    const int nkt = qt + 1;    // 128-key tiles

    load_tile(0, 0);

    for (int kt = 0; kt < nkt; kt++) {
        const int stg = kt & 1;
        CP_WAIT(0);
        __syncthreads();
        if (kt + 1 < nkt) load_tile(kt + 1, stg ^ 1);

        const uint32_t tile_b = sbase + FA_KV_OFF + stg * FA_STAGE_B;

        // ---- two 64-key halves, identical arithmetic to v3 ----
#pragma unroll
        for (int half = 0; half < 2; half++) {
            const int kb = kt * 128 + half * 64;
            if (kb > qrow_w + 15) break;   // kb monotone within tile

            const uint32_t ks_b = tile_b + (uint32_t)(half * 64) * FA_ROW_B;
            const uint32_t vs_b = tile_b + FA_K_ARR_B + (uint32_t)(half * 64) * FA_ROW_B;

            float s[8][4];
#pragma unroll
            for (int i = 0; i < 8; i++)
#pragma unroll
                for (int j = 0; j < 4; j++) s[i][j] = 0.f;

#pragma unroll
            for (int t = 0; t < 4; t++) {
                uint32_t q4[4];
                ldsm_x4(q4, q_w + t * 32);
#pragma unroll
                for (int pp = 0; pp < 4; pp++) {
                    const uint32_t ro = (uint32_t)(pp * 16 * FA_ROW_B + t * 32) + k_loff;
                    uint32_t k4[4];
                    ldsm_x4(k4, ks_b + ro);
                    mma_f16(s[2 * pp],     q4, k4[0], k4[1]);
                    mma_f16(s[2 * pp + 1], q4, k4[2], k4[3]);
                }
            }

            const int row_g0 = qrow_w + (lane >> 2);
            if (kb + 63 > qrow_w) {
#pragma unroll
                for (int nt = 0; nt < 8; nt++) {
                    const int colb = kb + nt * 8 + (lane & 3) * 2;
#pragma unroll
                    for (int i = 0; i < 4; i++) {
                        const int row = row_g0 + (i >> 1) * 8;
                        const int col = colb + (i & 1);
                        if (col > row) s[nt][i] = -CUDART_INF_F;
                    }
                }
            }

            float rmax[2];
            rmax[0] = rmax[1] = -CUDART_INF_F;
#pragma unroll
            for (int nt = 0; nt < 8; nt++) {
                rmax[0] = fmaxf(rmax[0], fmaxf(s[nt][0], s[nt][1]));
                rmax[1] = fmaxf(rmax[1], fmaxf(s[nt][2], s[nt][3]));
            }
#pragma unroll
            for (int off = 1; off <= 2; off <<= 1) {
                rmax[0] = fmaxf(rmax[0], __shfl_xor_sync(0xffffffffu, rmax[0], off));
                rmax[1] = fmaxf(rmax[1], __shfl_xor_sync(0xffffffffu, rmax[1], off));
            }

            float alpha[2], rsum[2];
#pragma unroll
            for (int i = 0; i < 2; i++) {
                float mn = fmaxf(m[i], rmax[i]);
                alpha[i] = ex2f((m[i] - mn) * SCL2E);
                m[i] = mn;
                rsum[i] = 0.f;
            }

#pragma unroll
            for (int nt = 0; nt < 8; nt++) {
                s[nt][0] = ex2f((s[nt][0] - m[0]) * SCL2E);
                s[nt][1] = ex2f((s[nt][1] - m[0]) * SCL2E);
                s[nt][2] = ex2f((s[nt][2] - m[1]) * SCL2E);
                s[nt][3] = ex2f((s[nt][3] - m[1]) * SCL2E);
                rsum[0] += s[nt][0] + s[nt][1];
                rsum[1] += s[nt][2] + s[nt][3];
            }
            l[0] = l[0] * alpha[0] + rsum[0];
            l[1] = l[1] * alpha[1] + rsum[1];
#pragma unroll
            for (int nt = 0; nt < 8; nt++) {
                o[nt][0] *= alpha[0]; o[nt][1] *= alpha[0];
                o[nt][2] *= alpha[1]; o[nt][3] *= alpha[1];
            }

#pragma unroll
            for (int t = 0; t < 4; t++) {
                uint32_t pa[4];
                pa[0] = pack_f16(s[2 * t][0],     s[2 * t][1]);
                pa[1] = pack_f16(s[2 * t][2],     s[2 * t][3]);
                pa[2] = pack_f16(s[2 * t + 1][0], s[2 * t + 1][1]);
                pa[3] = pack_f16(s[2 * t + 1][2], s[2 * t + 1][3]);
#pragma unroll
                for (int dp = 0; dp < 4; dp++) {
                    const uint32_t ro = (uint32_t)(t * 16 * FA_ROW_B + dp * 32) + v_loff;
                    uint32_t v4[4];
                    ldsm_x4_trans(v4, vs_b + ro);
                    mma_f16(o[2 * dp],     pa, v4[0], v4[1]);
                    mma_f16(o[2 * dp + 1], pa, v4[2], v4[3]);
                }
            }
        }
    }

    // ---- deferred l reduction over quad ----
#pragma unroll
    for (int off = 1; off <= 2; off <<= 1) {
        l[0] += __shfl_xor_sync(0xffffffffu, l[0], off);
        l[1] += __shfl_xor_sync(0xffffffffu, l[1], off);
    }

    // ---- epilogue: normalize, store fp16 ctx ----
    const float inv0 = 1.f / l[0];
    const float inv1 = 1.f / l[1];
    const int orow = q0_tok + wid * 16 + (lane >> 2);
    const int colb = h * HDIM + (lane & 3) * 2;
#pragma unroll
    for (int nt = 0; nt < 8; nt++) {
        const int col = colb + nt * 8;
        *(uint32_t*)(C + (size_t)orow * DMODEL + col) =
            pack_f16(o[nt][0] * inv0, o[nt][1] * inv0);
        *(uint32_t*)(C + (size_t)(orow + 8) * DMODEL + col) =
            pack_f16(o[nt][2] * inv1, o[nt][3] * inv1);
    }
}

// ---------------------------------------------------------------------------
// Launch
// ---------------------------------------------------------------------------
extern "C" void kernel_launch(void* const* d_in, const int* in_sizes, int n_in,
                              void* d_out, int out_size)
{
    const float* x  = (const float*)d_in[0];
    const float* wq = (const float*)d_in[1];
    const float* wk = (const float*)d_in[2];
    const float* wv = (const float*)d_in[3];
    const float* wo = (const float*)d_in[4];
    const float* bo = (const float*)d_in[5];
    float* out = (float*)d_out;

    __half *xh, *qh, *kh, *vh, *ch;
    __half *wqh, *wkh, *wvh, *woh;
    cudaGetSymbolAddress((void**)&xh,  g_xh);
    cudaGetSymbolAddress((void**)&qh,  g_qh);
    cudaGetSymbolAddress((void**)&kh,  g_kh);
    cudaGetSymbolAddress((void**)&vh,  g_vh);
    cudaGetSymbolAddress((void**)&ch,  g_ch);
    cudaGetSymbolAddress((void**)&wqh, g_wqh);
    cudaGetSymbolAddress((void**)&wkh, g_wkh);
    cudaGetSymbolAddress((void**)&wvh, g_wvh);
    cudaGetSymbolAddress((void**)&woh, g_woh);

    const int nx = TOKENS * DMODEL;

    // One prep launch: y==0 converts x (8192 blocks); y==1..4 weights (1024).
    prep_all_kernel<<<dim3(nx / 4 / 256, 5), 256>>>(
        x, wq, wk, wv, wo, xh, wqh, wkh, wvh, woh);

    cudaFuncSetAttribute(gemm_qkv,
                         cudaFuncAttributeMaxDynamicSharedMemorySize, G1_SMEM);
    cudaFuncSetAttribute(gemm_out,
                         cudaFuncAttributeMaxDynamicSharedMemorySize, G1_SMEM);

    gemm_qkv<<<dim3(DMODEL / 128, TOKENS / 128, 3), 256, G1_SMEM>>>(
        xh, wqh, wkh, wvh, qh, kh, vh);

    cudaFuncSetAttribute(flash_mma_kernel,
                         cudaFuncAttributeMaxDynamicSharedMemorySize, FA_SMEM);
    flash_mma_kernel<<<dim3(SEQ / 128, NHEADS, BATCH), 256, FA_SMEM>>>(
        qh, kh, vh, ch);

    gemm_out<<<dim3(DMODEL / 128, TOKENS / 128), 256, G1_SMEM>>>(
        ch, woh, bo, out);
}

// round 16
// speedup vs baseline: 1.0285x; 1.0285x over previous
#include <cuda_runtime.h>
#include <cuda_fp16.h>
#include <math_constants.h>
#include <cstdint>

// Problem constants
#define BATCH   4
#define SEQ     2048
#define DMODEL  1024
#define NHEADS  16
#define HDIM    64
#define TOKENS  (BATCH * SEQ)   // 8192

#define LOG2E 1.4426950408889634f
#define SCL2E (0.125f * LOG2E)   // softmax scale folded into exponent

// ---------------------------------------------------------------------------
// Scratch (allocation-free rule: __device__ globals)
// ---------------------------------------------------------------------------
__device__ __half g_xh [TOKENS * DMODEL];
__device__ __half g_qh [TOKENS * DMODEL];
__device__ __half g_kh [TOKENS * DMODEL];
__device__ __half g_vh [TOKENS * DMODEL];
__device__ __half g_ch [TOKENS * DMODEL];
__device__ __half g_wqh[DMODEL * DMODEL];
__device__ __half g_wkh[DMODEL * DMODEL];
__device__ __half g_wvh[DMODEL * DMODEL];
__device__ __half g_woh[DMODEL * DMODEL];

// ---------------------------------------------------------------------------
// PTX helpers (sm_80-baseline only: cp.async, ldmatrix, mma.sync)
// ---------------------------------------------------------------------------
__device__ __forceinline__ uint32_t smem_u32(const void* p) {
    uint32_t a;
    asm("{ .reg .u64 t; cvta.to.shared.u64 t, %1; cvt.u32.u64 %0, t; }"
        : "=r"(a) : "l"(p));
    return a;
}

__device__ __forceinline__ void cp_async16(uint32_t smem, const void* gmem) {
    asm volatile("cp.async.cg.shared.global [%0], [%1], 16;\n"
                 :: "r"(smem), "l"(gmem));
}
#define CP_COMMIT() asm volatile("cp.async.commit_group;\n" ::: "memory")
#define CP_WAIT(n)  asm volatile("cp.async.wait_group %0;\n" :: "n"(n) : "memory")

__device__ __forceinline__ void ldsm_x4(uint32_t* r, uint32_t addr) {
    asm volatile("ldmatrix.sync.aligned.m8n8.x4.shared.b16 {%0,%1,%2,%3}, [%4];"
                 : "=r"(r[0]), "=r"(r[1]), "=r"(r[2]), "=r"(r[3]) : "r"(addr));
}

__device__ __forceinline__ void ldsm_x4_trans(uint32_t* r, uint32_t addr) {
    asm volatile("ldmatrix.sync.aligned.m8n8.x4.trans.shared.b16 {%0,%1,%2,%3}, [%4];"
                 : "=r"(r[0]), "=r"(r[1]), "=r"(r[2]), "=r"(r[3]) : "r"(addr));
}

__device__ __forceinline__ void mma_f16(float* c, const uint32_t* a,
                                        uint32_t b0, uint32_t b1) {
    asm volatile(
        "mma.sync.aligned.m16n8k16.row.col.f32.f16.f16.f32 "
        "{%0,%1,%2,%3}, {%4,%5,%6,%7}, {%8,%9}, {%0,%1,%2,%3};"
        : "+f"(c[0]), "+f"(c[1]), "+f"(c[2]), "+f"(c[3])
        : "r"(a[0]), "r"(a[1]), "r"(a[2]), "r"(a[3]), "r"(b0), "r"(b1));
}

__device__ __forceinline__ uint32_t pack_f16(float x, float y) {
    __half2 t = __floats2half2_rn(x, y);
    return *(uint32_t*)&t;
}

// Single-MUFU exp2 (approx, ftz). -inf -> 0, which is what the mask needs.
__device__ __forceinline__ float ex2f(float x) {
    float r;
    asm("ex2.approx.ftz.f32 %0, %1;" : "=f"(r) : "f"(x));
    return r;
}

// ---------------------------------------------------------------------------
// Preprocessing: one flat launch converts x and all 4 weights to fp16.
// Elements 0..nx-1 -> x; nx..nx+4*nw-1 -> weights (nw each).
// ---------------------------------------------------------------------------
#define NX (TOKENS * DMODEL)   // 8388608
#define NW (DMODEL * DMODEL)   // 1048576

__global__ void prep_all_kernel(
    const float* __restrict__ x,
    const float* __restrict__ wq, const float* __restrict__ wk,
    const float* __restrict__ wv, const float* __restrict__ wo,
    __half* __restrict__ xh,
    __half* __restrict__ wqh, __half* __restrict__ wkh,
    __half* __restrict__ wvh, __half* __restrict__ woh)
{
    int i = (blockIdx.x * blockDim.x + threadIdx.x) * 4;
    const float* in;
    __half* out;
    int off;
    if (i < NX) {
        in = x; out = xh; off = i;
    } else {
        int j = i - NX;
        int w = j >> 20;          // j / NW  (NW = 2^20)
        off = j & (NW - 1);       // j % NW
        in  = (w == 0) ? wq : (w == 1) ? wk : (w == 2) ? wv : wo;
        out = (w == 0) ? wqh : (w == 1) ? wkh : (w == 2) ? wvh : woh;
    }
    float4 v = *(const float4*)(in + off);
    ((__half2*)(out + off))[0] = __floats2half2_rn(v.x, v.y);
    ((__half2*)(out + off))[1] = __floats2half2_rn(v.z, v.w);
}

// ---------------------------------------------------------------------------
// Single-pass fp16 GEMM core: CTA 128x128, BK=64, 256 threads (8 warps,
// 2x4), warp tile 64x32, 3-stage cp.async (110,592 B), launch_bounds(256,2).
// (round-14 config, known good)
// ---------------------------------------------------------------------------
#define GK_BK       64
#define GK_ROW_B    144
#define GK_TILE_B   (128 * GK_ROW_B)           // 18432
#define GK_NCHUNKS  (DMODEL / GK_BK)           // 16
#define G1_STAGE_B  (2 * GK_TILE_B)            // 36864
#define G1_STAGES   3
#define G1_SMEM     (G1_STAGES * G1_STAGE_B)   // 110592

__device__ __forceinline__ void g1_mainloop(
    const __half* __restrict__ A, const __half* __restrict__ B,
    int bm, int bn, uint32_t sbase, int tid, float acc[4][4][4])
{
    const int wid  = tid >> 5;
    const int lane = tid & 31;
    const int warp_m = wid >> 2;
    const int warp_n = wid & 3;

    auto load_chunk = [&](int c, int st) {
        const int k0 = c * GK_BK;
        const uint32_t sb = sbase + st * G1_STAGE_B;
#pragma unroll
        for (int i = tid; i < 1024; i += 256) {
            const int r = i >> 3;
            const int q = i & 7;
            cp_async16(sb + r * GK_ROW_B + q * 16,
                       A + (size_t)(bm + r) * DMODEL + k0 + q * 8);
            cp_async16(sb + GK_TILE_B + r * GK_ROW_B + q * 16,
                       B + (size_t)(bn + r) * DMODEL + k0 + q * 8);
        }
        CP_COMMIT();
    };

    load_chunk(0, 0);
    load_chunk(1, 1);

    const uint32_t lrow16 = (uint32_t)(lane & 15);
    const uint32_t lcolb  = (uint32_t)((lane >> 4) << 4);

    for (int c = 0; c < GK_NCHUNKS; c++) {
        const int st = c % G1_STAGES;
        if (c + 1 < GK_NCHUNKS) { CP_WAIT(1); } else { CP_WAIT(0); }
        __syncthreads();
        if (c + 2 < GK_NCHUNKS) load_chunk(c + 2, (c + 2) % G1_STAGES);

        const uint32_t stg = sbase + st * G1_STAGE_B;
        const uint32_t a_r = (uint32_t)(warp_m * 64) + lrow16;
        const uint32_t b_r = (uint32_t)(warp_n * 32) + lrow16;

#pragma unroll
        for (int ks = 0; ks < 4; ks++) {
            const uint32_t kb = lcolb + ks * 32;
            uint32_t ah[4][4], bb[2][4];
#pragma unroll
            for (int mi = 0; mi < 4; mi++)
                ldsm_x4(ah[mi], stg + (a_r + mi * 16) * GK_ROW_B + kb);
#pragma unroll
            for (int p = 0; p < 2; p++)
                ldsm_x4(bb[p], stg + GK_TILE_B + (b_r + p * 16) * GK_ROW_B + kb);
#pragma unroll
            for (int mi = 0; mi < 4; mi++)
#pragma unroll
                for (int ni = 0; ni < 4; ni++) {
                    const int p = ni >> 1, s = ni & 1;
                    mma_f16(acc[mi][ni], ah[mi], bb[p][s], bb[p][s + 2]);
                }
        }
        __syncthreads();
    }
}

// ---------------------------------------------------------------------------
// Fused QKV projection (single-pass fp16): grid.z selects W/output.
// ---------------------------------------------------------------------------
__global__ __launch_bounds__(256, 2) void gemm_qkv(
    const __half* __restrict__ xh,
    const __half* __restrict__ wqh, const __half* __restrict__ wkh,
    const __half* __restrict__ wvh,
    __half* __restrict__ qh, __half* __restrict__ kh, __half* __restrict__ vh)
{
    extern __shared__ char smem[];
    const uint32_t sbase = smem_u32(smem);
    const int tid = threadIdx.x;
    const int bm = blockIdx.y * 128;
    const int bn = blockIdx.x * 128;

    const __half* B;
    __half* C;
    if (blockIdx.z == 0)      { B = wqh; C = qh; }
    else if (blockIdx.z == 1) { B = wkh; C = kh; }
    else                      { B = wvh; C = vh; }

    float acc[4][4][4];
#pragma unroll
    for (int i = 0; i < 4; i++)
#pragma unroll
        for (int j = 0; j < 4; j++)
#pragma unroll
            for (int r = 0; r < 4; r++) acc[i][j][r] = 0.f;

    g1_mainloop(xh, B, bm, bn, sbase, tid, acc);

    const int wid  = tid >> 5;
    const int lane = tid & 31;
    const int warp_m = wid >> 2;
    const int warp_n = wid & 3;
    const int er = lane >> 2;
    const int ec = (lane & 3) * 2;
#pragma unroll
    for (int mi = 0; mi < 4; mi++) {
        const int row0 = bm + warp_m * 64 + mi * 16 + er;
#pragma unroll
        for (int ni = 0; ni < 4; ni++) {
            const int col = bn + warp_n * 32 + ni * 8 + ec;
            *(uint32_t*)(C + (size_t)row0 * DMODEL + col) =
                pack_f16(acc[mi][ni][0], acc[mi][ni][1]);
            *(uint32_t*)(C + (size_t)(row0 + 8) * DMODEL + col) =
                pack_f16(acc[mi][ni][2], acc[mi][ni][3]);
        }
    }
}

// ---------------------------------------------------------------------------
// Output projection (single-pass fp16): fp32 out + bias.
// ---------------------------------------------------------------------------
__global__ __launch_bounds__(256, 2) void gemm_out(
    const __half* __restrict__ Ah, const __half* __restrict__ Bh,
    const float* __restrict__ bias, float* __restrict__ C)
{
    extern __shared__ char smem[];
    const uint32_t sbase = smem_u32(smem);
    const int tid = threadIdx.x;
    const int bm = blockIdx.y * 128;
    const int bn = blockIdx.x * 128;

    float acc[4][4][4];
#pragma unroll
    for (int i = 0; i < 4; i++)
#pragma unroll
        for (int j = 0; j < 4; j++)
#pragma unroll
            for (int r = 0; r < 4; r++) acc[i][j][r] = 0.f;

    g1_mainloop(Ah, Bh, bm, bn, sbase, tid, acc);

    const int wid  = tid >> 5;
    const int lane = tid & 31;
    const int warp_m = wid >> 2;
    const int warp_n = wid & 3;
    const int er = lane >> 2;
    const int ec = (lane & 3) * 2;
#pragma unroll
    for (int mi = 0; mi < 4; mi++) {
        const int row0 = bm + warp_m * 64 + mi * 16 + er;
#pragma unroll
        for (int ni = 0; ni < 4; ni++) {
            const int col = bn + warp_n * 32 + ni * 8 + ec;
            const float b0 = bias[col];
            const float b1 = bias[col + 1];
            float2 v0 = make_float2(acc[mi][ni][0] + b0, acc[mi][ni][1] + b1);
            float2 v1 = make_float2(acc[mi][ni][2] + b0, acc[mi][ni][3] + b1);
            *(float2*)(C + (size_t)row0 * DMODEL + col)       = v0;
            *(float2*)(C + (size_t)(row0 + 8) * DMODEL + col) = v1;
        }
    }
}

// ---------------------------------------------------------------------------
// Flash attention v3 (causal): fp16 single-pass MMA, fp32 softmax with
// single-MUFU ex2.approx. 64-key tiles, 4-stage cp.async pipeline
// (round-14 config, known good). LPT schedule: qt = 15 - blockIdx.x so
// heavy causal tiles launch first (better last-wave packing).
// ---------------------------------------------------------------------------
#define FA_ROW_B    144
#define FA_Q_B      (128 * FA_ROW_B)        // 18432
#define FA_KV_ARR_B (64 * FA_ROW_B)         // 9216
#define FA_STAGE_B  (2 * FA_KV_ARR_B)       // 18432
#define FA_NSTAGES  4
#define FA_KV_OFF   FA_Q_B
#define FA_SMEM     (FA_Q_B + FA_NSTAGES * FA_STAGE_B)  // 92160

__global__ __launch_bounds__(256, 2) void flash_mma_kernel(
    const __half* __restrict__ Q, const __half* __restrict__ K,
    const __half* __restrict__ V, __half* __restrict__ C)
{
    extern __shared__ char fsm[];
    const uint32_t sbase = smem_u32(fsm);

    const int tid  = threadIdx.x;
    const int wid  = tid >> 5;
    const int lane = tid & 31;
    const int qt = (SEQ / 128 - 1) - blockIdx.x;   // LPT: heavy tiles first
    const int h  = blockIdx.y;
    const int b  = blockIdx.z;

    const int q0_tok = b * SEQ + qt * 128;
    const int qrow_w = qt * 128 + wid * 16;

    {
        const __half* Qg = Q + (size_t)q0_tok * DMODEL + h * HDIM;
#pragma unroll
        for (int i = tid; i < 1024; i += 256) {
            const int r  = i >> 3;
            const int c8 = i & 7;
            cp_async16(sbase + r * FA_ROW_B + c8 * 16,
                       Qg + (size_t)r * DMODEL + c8 * 8);
        }
        CP_COMMIT();
    }

    float o[8][4];
    float m[2], l[2];
#pragma unroll
    for (int i = 0; i < 8; i++)
#pragma unroll
        for (int j = 0; j < 4; j++) o[i][j] = 0.f;
    m[0] = m[1] = -CUDART_INF_F;
    l[0] = l[1] = 0.f;

    const uint32_t a_loff = (uint32_t)((lane & 15) * FA_ROW_B + ((lane >> 4) << 4));
    const uint32_t k_loff = (uint32_t)(((lane & 7) + ((lane >> 4) << 3)) * FA_ROW_B
                                       + (((lane >> 3) & 1) << 4));
    const uint32_t v_loff = (uint32_t)(((lane & 7) + (((lane >> 3) & 1) << 3)) * FA_ROW_B
                                       + ((lane >> 4) << 4));

    const uint32_t q_w = sbase + (uint32_t)(wid * 16) * FA_ROW_B + a_loff;

    const __half* Kh = K + h * HDIM;
    const __half* Vh = V + h * HDIM;

    auto load_tile = [&](int kt, int stg) {
        const size_t tok0 = (size_t)(b * SEQ + kt * 64);
        const uint32_t sb = sbase + FA_KV_OFF + stg * FA_STAGE_B;
#pragma unroll
        for (int i = tid; i < 512; i += 256) {
            const int r  = i >> 3;
            const int c8 = i & 7;
            cp_async16(sb + r * FA_ROW_B + c8 * 16,
                       Kh + (tok0 + r) * DMODEL + c8 * 8);
            cp_async16(sb + FA_KV_ARR_B + r * FA_ROW_B + c8 * 16,
                       Vh + (tok0 + r) * DMODEL + c8 * 8);
        }
        CP_COMMIT();
    };

    const int nkt = 2 * qt + 2;

#pragma unroll
    for (int p = 0; p < 3; p++) {
        if (p < nkt) load_tile(p, p);
        else         CP_COMMIT();
    }

    for (int kt = 0; kt < nkt; kt++) {
        const int kb = kt * 64;
        const int stg = kt & 3;
        CP_WAIT(2);
        __syncthreads();
        if (kt + 3 < nkt) load_tile(kt + 3, (kt + 3) & 3);
        else              CP_COMMIT();

        if (kb > qrow_w + 15) continue;

        const uint32_t ks_b = sbase + FA_KV_OFF + stg * FA_STAGE_B;
        const uint32_t vs_b = ks_b + FA_KV_ARR_B;

        float s[8][4];
#pragma unroll
        for (int i = 0; i < 8; i++)
#pragma unroll
            for (int j = 0; j < 4; j++) s[i][j] = 0.f;

#pragma unroll
        for (int t = 0; t < 4; t++) {
            uint32_t q4[4];
            ldsm_x4(q4, q_w + t * 32);
#pragma unroll
            for (int pp = 0; pp < 4; pp++) {
                const uint32_t ro = (uint32_t)(pp * 16 * FA_ROW_B + t * 32) + k_loff;
                uint32_t k4[4];
                ldsm_x4(k4, ks_b + ro);
                mma_f16(s[2 * pp],     q4, k4[0], k4[1]);
                mma_f16(s[2 * pp + 1], q4, k4[2], k4[3]);
            }
        }

        const int row_g0 = qrow_w + (lane >> 2);
        if (kb + 63 > qrow_w) {
#pragma unroll
            for (int nt = 0; nt < 8; nt++) {
                const int colb = kb + nt * 8 + (lane & 3) * 2;
#pragma unroll
                for (int i = 0; i < 4; i++) {
                    const int row = row_g0 + (i >> 1) * 8;
                    const int col = colb + (i & 1);
                    if (col > row) s[nt][i] = -CUDART_INF_F;
                }
            }
        }

        float rmax[2];
        rmax[0] = rmax[1] = -CUDART_INF_F;
#pragma unroll
        for (int nt = 0; nt < 8; nt++) {
            rmax[0] = fmaxf(rmax[0], fmaxf(s[nt][0], s[nt][1]));
            rmax[1] = fmaxf(rmax[1], fmaxf(s[nt][2], s[nt][3]));
        }
#pragma unroll
        for (int off = 1; off <= 2; off <<= 1) {
            rmax[0] = fmaxf(rmax[0], __shfl_xor_sync(0xffffffffu, rmax[0], off));
            rmax[1] = fmaxf(rmax[1], __shfl_xor_sync(0xffffffffu, rmax[1], off));
        }

        float alpha[2], rsum[2];
#pragma unroll
        for (int i = 0; i < 2; i++) {
            float mn = fmaxf(m[i], rmax[i]);
            alpha[i] = ex2f((m[i] - mn) * SCL2E);
            m[i] = mn;
            rsum[i] = 0.f;
        }

#pragma unroll
        for (int nt = 0; nt < 8; nt++) {
            s[nt][0] = ex2f((s[nt][0] - m[0]) * SCL2E);
            s[nt][1] = ex2f((s[nt][1] - m[0]) * SCL2E);
            s[nt][2] = ex2f((s[nt][2] - m[1]) * SCL2E);
            s[nt][3] = ex2f((s[nt][3] - m[1]) * SCL2E);
            rsum[0] += s[nt][0] + s[nt][1];
            rsum[1] += s[nt][2] + s[nt][3];
        }
        l[0] = l[0] * alpha[0] + rsum[0];
        l[1] = l[1] * alpha[1] + rsum[1];
#pragma unroll
        for (int nt = 0; nt < 8; nt++) {
            o[nt][0] *= alpha[0]; o[nt][1] *= alpha[0];
            o[nt][2] *= alpha[1]; o[nt][3] *= alpha[1];
        }

#pragma unroll
        for (int t = 0; t < 4; t++) {
            uint32_t pa[4];
            pa[0] = pack_f16(s[2 * t][0],     s[2 * t][1]);
            pa[1] = pack_f16(s[2 * t][2],     s[2 * t][3]);
            pa[2] = pack_f16(s[2 * t + 1][0], s[2 * t + 1][1]);
            pa[3] = pack_f16(s[2 * t + 1][2], s[2 * t + 1][3]);
#pragma unroll
            for (int dp = 0; dp < 4; dp++) {
                const uint32_t ro = (uint32_t)(t * 16 * FA_ROW_B + dp * 32) + v_loff;
                uint32_t v4[4];
                ldsm_x4_trans(v4, vs_b + ro);
                mma_f16(o[2 * dp],     pa, v4[0], v4[1]);
                mma_f16(o[2 * dp + 1], pa, v4[2], v4[3]);
            }
        }
    }

#pragma unroll
    for (int off = 1; off <= 2; off <<= 1) {
        l[0] += __shfl_xor_sync(0xffffffffu, l[0], off);
        l[1] += __shfl_xor_sync(0xffffffffu, l[1], off);
    }

    const float inv0 = 1.f / l[0];
    const float inv1 = 1.f / l[1];
    const int orow = q0_tok + wid * 16 + (lane >> 2);
    const int colb = h * HDIM + (lane & 3) * 2;
#pragma unroll
    for (int nt = 0; nt < 8; nt++) {
        const int col = colb + nt * 8;
        *(uint32_t*)(C + (size_t)orow * DMODEL + col) =
            pack_f16(o[nt][0] * inv0, o[nt][1] * inv0);
        *(uint32_t*)(C + (size_t)(orow + 8) * DMODEL + col) =
            pack_f16(o[nt][2] * inv1, o[nt][3] * inv1);
    }
}

// ---------------------------------------------------------------------------
// Launch
// ---------------------------------------------------------------------------
extern "C" void kernel_launch(void* const* d_in, const int* in_sizes, int n_in,
                              void* d_out, int out_size)
{
    const float* x  = (const float*)d_in[0];
    const float* wq = (const float*)d_in[1];
    const float* wk = (const float*)d_in[2];
    const float* wv = (const float*)d_in[3];
    const float* wo = (const float*)d_in[4];
    const float* bo = (const float*)d_in[5];
    float* out = (float*)d_out;

    __half *xh, *qh, *kh, *vh, *ch;
    __half *wqh, *wkh, *wvh, *woh;
    cudaGetSymbolAddress((void**)&xh,  g_xh);
    cudaGetSymbolAddress((void**)&qh,  g_qh);
    cudaGetSymbolAddress((void**)&kh,  g_kh);
    cudaGetSymbolAddress((void**)&vh,  g_vh);
    cudaGetSymbolAddress((void**)&ch,  g_ch);
    cudaGetSymbolAddress((void**)&wqh, g_wqh);
    cudaGetSymbolAddress((void**)&wkh, g_wkh);
    cudaGetSymbolAddress((void**)&wvh, g_wvh);
    cudaGetSymbolAddress((void**)&woh, g_woh);

    // One flat prep launch: (NX + 4*NW)/4/256 = 12288 blocks, no waste.
    prep_all_kernel<<<(NX + 4 * NW) / 4 / 256, 256>>>(
        x, wq, wk, wv, wo, xh, wqh, wkh, wvh, woh);

    cudaFuncSetAttribute(gemm_qkv,
                         cudaFuncAttributeMaxDynamicSharedMemorySize, G1_SMEM);
    cudaFuncSetAttribute(gemm_out,
                         cudaFuncAttributeMaxDynamicSharedMemorySize, G1_SMEM);

    gemm_qkv<<<dim3(DMODEL / 128, TOKENS / 128, 3), 256, G1_SMEM>>>(
        xh, wqh, wkh, wvh, qh, kh, vh);

    cudaFuncSetAttribute(flash_mma_kernel,
                         cudaFuncAttributeMaxDynamicSharedMemorySize, FA_SMEM);
    flash_mma_kernel<<<dim3(SEQ / 128, NHEADS, BATCH), 256, FA_SMEM>>>(
        qh, kh, vh, ch);

    gemm_out<<<dim3(DMODEL / 128, TOKENS / 128), 256, G1_SMEM>>>(
        ch, woh, bo, out);
}